// round 14
// baseline (speedup 1.0000x reference)
#include <cuda_runtime.h>
#include <cuda_fp16.h>
#include <cstdint>
#include <cstddef>

#define S_LEN 512
#define BATCH 64
#define EMB   512
#define HID   1024
#define G4    4096
#define NTAG  13
#define RBLK  64

// ---------------- scratch (device globals: no allocs allowed) ----------------
__device__ __half g_Wih16[(size_t)NTAG * G4 * EMB];
__device__ __half g_Whh16[(size_t)NTAG * G4 * HID];
__device__ float  g_bias[NTAG * G4];
__device__ __half g_x16[(size_t)S_LEN * BATCH * EMB];
__device__ __half g_pre16[(size_t)S_LEN * BATCH * G4];
__device__ __half g_h[2][BATCH * HID];
__device__ unsigned int g_bar;
__device__ int g_sel256;
__device__ int g_order[S_LEN];

// ---------------- helpers ----------------
__device__ __forceinline__ void cp16_ca(void* dst, const void* src) {
    unsigned d = (unsigned)__cvta_generic_to_shared(dst);
    asm volatile("cp.async.ca.shared.global [%0], [%1], 16;\n" :: "r"(d), "l"(src));
}
__device__ __forceinline__ void cp16_cg(void* dst, const void* src) {
    unsigned d = (unsigned)__cvta_generic_to_shared(dst);
    asm volatile("cp.async.cg.shared.global [%0], [%1], 16;\n" :: "r"(d), "l"(src));
}
#define CP_COMMIT() asm volatile("cp.async.commit_group;\n" ::)
#define CP_WAIT(n)  asm volatile("cp.async.wait_group %0;\n" :: "n"(n))

__device__ __forceinline__ void mma_16816(float d[4], const unsigned a[4], const unsigned b[2]) {
    asm volatile(
        "mma.sync.aligned.m16n8k16.row.col.f32.f16.f16.f32 "
        "{%0,%1,%2,%3}, {%4,%5,%6,%7}, {%8,%9}, {%0,%1,%2,%3};\n"
        : "+f"(d[0]), "+f"(d[1]), "+f"(d[2]), "+f"(d[3])
        : "r"(a[0]), "r"(a[1]), "r"(a[2]), "r"(a[3]), "r"(b[0]), "r"(b[1]));
}

__device__ __forceinline__ float fsig(float x) {
    return __fdividef(1.f, 1.f + __expf(-x));
}
__device__ __forceinline__ float ftanh(float x) {
    return 2.f * __fdividef(1.f, 1.f + __expf(-2.f * x)) - 1.f;
}

// ---------------- prep 1: cast Wih + bias ----------------
__global__ void k_prep1(const float* __restrict__ Wih,
                        const float* __restrict__ bih, const float* __restrict__ bhh) {
    const size_t tid0 = (size_t)blockIdx.x * blockDim.x + threadIdx.x;
    const size_t stride = (size_t)gridDim.x * blockDim.x;
    const size_t n4 = (size_t)NTAG * G4 * EMB / 4;
    for (size_t i = tid0; i < n4; i += stride) {
        float4 a = ((const float4*)Wih)[i];
        __half2* o = (__half2*)(g_Wih16 + i * 4);
        o[0] = __floats2half2_rn(a.x, a.y);
        o[1] = __floats2half2_rn(a.z, a.w);
    }
    for (size_t i = tid0; i < (size_t)NTAG * G4; i += stride)
        g_bias[i] = bih[i] + bhh[i];
}

// ---------------- prep 2: cast Whh + gather x + init + order + pick ----------------
__global__ void k_prep2(const float* __restrict__ Whh,
                        const int* __restrict__ tokens, const float* __restrict__ emb,
                        const int* __restrict__ tags,
                        const float* __restrict__ p2a, const float* __restrict__ p2b) {
    const size_t tid0 = (size_t)blockIdx.x * blockDim.x + threadIdx.x;
    const size_t stride = (size_t)gridDim.x * blockDim.x;
    const size_t n4 = (size_t)NTAG * G4 * HID / 4;
    for (size_t i = tid0; i < n4; i += stride) {
        float4 a = ((const float4*)Whh)[i];
        __half2* o = (__half2*)(g_Whh16 + i * 4);
        o[0] = __floats2half2_rn(a.x, a.y);
        o[1] = __floats2half2_rn(a.z, a.w);
    }
    // gather: idx over S*B*(EMB/4)
    const size_t gtot = (size_t)S_LEN * BATCH * (EMB / 4);
    for (size_t idx = tid0; idx < gtot; idx += stride) {
        const int i = (int)(idx & (EMB / 4 - 1));
        const size_t r = idx >> 7;
        const int b = (int)(r & (BATCH - 1));
        const int s = (int)(r >> 6);
        const int tok = tokens[b * S_LEN + s];
        float4 v = ((const float4*)(emb + (size_t)tok * EMB))[i];
        __half2* dst = (__half2*)(g_x16 + ((size_t)s * BATCH + b) * EMB) + i * 2;
        dst[0] = __floats2half2_rn(v.x, v.y);
        dst[1] = __floats2half2_rn(v.z, v.w);
    }
    // zero h[0]
    for (size_t i = tid0; i < BATCH * HID / 2; i += stride)
        ((unsigned*)&g_h[0][0])[i] = 0u;
    // serial bits
    if (blockIdx.x == 0 && threadIdx.x == 0) {
        int cnt[NTAG];
        for (int t = 0; t < NTAG; t++) cnt[t] = 0;
        for (int s = 0; s < S_LEN; s++) cnt[tags[s]]++;
        int pos[NTAG]; int accp = 0;
        for (int t = 0; t < NTAG; t++) { pos[t] = accp; accp += cnt[t]; }
        for (int s = 0; s < S_LEN; s++) g_order[pos[tags[s]]++] = s;
        float sa = 0.f, sb = 0.f;
        for (int i = 0; i < 256; i++) { sa += fabsf(p2a[i]); sb += fabsf(p2b[i]); }
        g_sel256 = (sa <= sb) ? 1 : 0;
        g_bar = 0u;
    }
}

// ---------------- phase A: input GEMM, tag-paired steps (M=128, N=128, K=512) ----------------
__device__ __forceinline__ void input_pass(
    int s0, int s1, int tag, int j0, int tid,
    __half (*Asm)[128][40], __half (*Bsm)[128][40], float* bsm,
    bool wlo, bool whi)
{
    const __half* Ag0 = g_x16 + (size_t)s0 * BATCH * EMB;
    const __half* Ag1 = g_x16 + (size_t)s1 * BATCH * EMB;
    const __half* Bg = g_Wih16 + ((size_t)tag * G4 + (size_t)j0) * EMB;
    if (tid < 128) bsm[tid] = g_bias[tag * G4 + j0 + tid];

    const int cr = tid >> 2;            // 0..63
    const int cc = (tid & 3) * 8;       // chunk col offset (32-col chunk)

    float acc[4][4][4];
    #pragma unroll
    for (int mi = 0; mi < 4; mi++)
        #pragma unroll
        for (int ni = 0; ni < 4; ni++)
            #pragma unroll
            for (int q = 0; q < 4; q++) acc[mi][ni][q] = 0.f;

    cp16_ca(&Asm[0][cr][cc],      Ag0 + (size_t)cr * EMB + cc);
    cp16_ca(&Asm[0][cr + 64][cc], Ag1 + (size_t)cr * EMB + cc);
    cp16_ca(&Bsm[0][cr][cc],      Bg + (size_t)cr * EMB + cc);
    cp16_ca(&Bsm[0][cr + 64][cc], Bg + (size_t)(cr + 64) * EMB + cc);
    CP_COMMIT();

    const int wid = tid >> 5, lane = tid & 31;
    const int wm = wid >> 2, wn = wid & 3;      // 2 x 4: M64 x N32 per warp
    const int g = lane >> 2, t = lane & 3;

    #pragma unroll 1
    for (int ch = 0; ch < 16; ch++) {
        if (ch < 15) {
            const int kk = (ch + 1) * 32;
            const int st = (ch + 1) & 1;
            cp16_ca(&Asm[st][cr][cc],      Ag0 + (size_t)cr * EMB + kk + cc);
            cp16_ca(&Asm[st][cr + 64][cc], Ag1 + (size_t)cr * EMB + kk + cc);
            cp16_ca(&Bsm[st][cr][cc],      Bg + (size_t)cr * EMB + kk + cc);
            cp16_ca(&Bsm[st][cr + 64][cc], Bg + (size_t)(cr + 64) * EMB + kk + cc);
            CP_COMMIT();
            CP_WAIT(1);
        } else {
            CP_WAIT(0);
        }
        __syncthreads();
        const int st = ch & 1;
        #pragma unroll
        for (int ks = 0; ks < 2; ks++) {
            const int k = ks * 16;
            unsigned a[4][4];
            #pragma unroll
            for (int mi = 0; mi < 4; mi++) {
                const int r0 = wm * 64 + mi * 16 + g;
                a[mi][0] = *(const unsigned*)&Asm[st][r0][k + 2 * t];
                a[mi][1] = *(const unsigned*)&Asm[st][r0 + 8][k + 2 * t];
                a[mi][2] = *(const unsigned*)&Asm[st][r0][k + 8 + 2 * t];
                a[mi][3] = *(const unsigned*)&Asm[st][r0 + 8][k + 8 + 2 * t];
            }
            #pragma unroll
            for (int ni = 0; ni < 4; ni++) {
                const int n = wn * 32 + ni * 8 + g;
                unsigned b[2];
                b[0] = *(const unsigned*)&Bsm[st][n][k + 2 * t];
                b[1] = *(const unsigned*)&Bsm[st][n][k + 8 + 2 * t];
                #pragma unroll
                for (int mi = 0; mi < 4; mi++) mma_16816(acc[mi][ni], a[mi], b);
            }
        }
        __syncthreads();
    }

    const bool w = (wm == 0) ? wlo : whi;
    const int sOut = (wm == 0) ? s0 : s1;
    if (w) {
        #pragma unroll
        for (int mi = 0; mi < 4; mi++) {
            const int lr = mi * 16 + g;       // local row in step (0..63)
            #pragma unroll
            for (int ni = 0; ni < 4; ni++) {
                const int col = wn * 32 + ni * 8 + 2 * t;
                const float b0v = bsm[col], b1v = bsm[col + 1];
                *(__half2*)&g_pre16[((size_t)sOut * BATCH + lr) * G4 + j0 + col] =
                    __floats2half2_rn(acc[mi][ni][0] + b0v, acc[mi][ni][1] + b1v);
                *(__half2*)&g_pre16[((size_t)sOut * BATCH + lr + 8) * G4 + j0 + col] =
                    __floats2half2_rn(acc[mi][ni][2] + b0v, acc[mi][ni][3] + b1v);
            }
        }
    }
    __syncthreads();
}

__global__ __launch_bounds__(256) void k_input_pair(const int* __restrict__ tags) {
    __shared__ __half Asm[2][128][40];
    __shared__ __half Bsm[2][128][40];
    __shared__ float  bsm[128];
    const int jt = blockIdx.x;              // 0..31
    const int p  = blockIdx.y;              // 0..255
    const int j0 = jt * 128;
    const int tid = threadIdx.x;
    const int s0 = g_order[2 * p], s1 = g_order[2 * p + 1];
    const int t0 = tags[s0], t1 = tags[s1];
    if (t0 == t1) {
        input_pass(s0, s1, t0, j0, tid, Asm, Bsm, bsm, true, true);
    } else {
        input_pass(s0, s1, t0, j0, tid, Asm, Bsm, bsm, true, false);
        input_pass(s0, s1, t1, j0, tid, Asm, Bsm, bsm, false, true);
    }
}

// ---------------- phase B: persistent recurrent (64 blocks x 16 units, dyn smem) ----------------
#define RSM_A   (2 * 64 * 136)                 // halves
#define RSM_B   (2 * 64 * 136)
#define RSM_P   (64 * 64)
#define RSM_G   (64 * 65)                      // floats
#define RSM_BYTES ((RSM_A + RSM_B + RSM_P) * 2 + (RSM_G + 1024) * 4 + S_LEN * 4)

__global__ __launch_bounds__(256) void k_recurrent(const int* __restrict__ tags) {
    extern __shared__ __align__(16) unsigned char dsm_raw[];
    __half* Abuf = (__half*)dsm_raw;
    __half* Bbuf = Abuf + RSM_A;
    __half* psm  = Bbuf + RSM_B;
    float*  gsm  = (float*)(psm + RSM_P);
    float*  csm  = gsm + RSM_G;
    int*    tsm  = (int*)(csm + 1024);
#define ASMr(st,r,c) Abuf[((st) * 64 + (r)) * 136 + (c)]
#define BSMr(st,r,c) Bbuf[((st) * 64 + (r)) * 136 + (c)]
#define PSMr(r,c)    psm[(r) * 64 + (c)]
#define GSMr(r,c)    gsm[(r) * 65 + (c)]

    const int tid = threadIdx.x;
    const int u0  = blockIdx.x * 16;

    for (int i = tid; i < S_LEN; i += 256) tsm[i] = tags[i];
    for (int i = tid; i < 1024; i += 256) csm[i] = 0.f;
    __syncthreads();

    const int wid = tid >> 5, lane = tid & 31;
    const int wm = wid >> 2, wn = wid & 3;     // 2 x 4: M32 x N16 per warp
    const int g = lane >> 2, t = lane & 3;

    // copy maps: chunk = 128 cols (16 ops/row), 64 rows, 4 ops/thread
    const int q    = tid >> 4;                  // 0..15 (row within group of 16)
    const int acol = (tid & 15) * 8;
    // B row for (r, q): brow = q + r*16 -> gate r, unit u0+q
    size_t boff[4];
    #pragma unroll
    for (int r = 0; r < 4; r++)
        boff[r] = ((size_t)r * 1024 + u0 + q) * HID + acol;
    const int pb = tid >> 2, pg = tid & 3;

    for (int s = 0; s < S_LEN; s++) {
        const int tag = tsm[s];
        const __half* Wg = g_Whh16 + (size_t)tag * G4 * HID;
        const __half* hg = g_h[s & 1];

        float acc[2][2][4];
        #pragma unroll
        for (int mi = 0; mi < 2; mi++)
            #pragma unroll
            for (int ni = 0; ni < 2; ni++)
                #pragma unroll
                for (int z = 0; z < 4; z++) acc[mi][ni][z] = 0.f;

        // chunk 0 group: A, B, pre tile
        #pragma unroll
        for (int r = 0; r < 4; r++) {
            cp16_cg(&ASMr(0, q + r * 16, acol), hg + (size_t)(q + r * 16) * HID + acol);
            cp16_ca(&BSMr(0, q + r * 16, acol), Wg + boff[r]);
        }
        {
            const __half* psrc = g_pre16 + ((size_t)s * BATCH + pb) * G4 + (size_t)pg * 1024 + u0;
            cp16_ca(&PSMr(pb, pg * 16), psrc);
            cp16_ca(&PSMr(pb, pg * 16 + 8), psrc + 8);
        }
        CP_COMMIT();

        #pragma unroll 1
        for (int ch = 0; ch < 8; ch++) {
            if (ch < 7) {
                const int kk = (ch + 1) * 128;
                const int st = (ch + 1) & 1;
                #pragma unroll
                for (int r = 0; r < 4; r++) {
                    cp16_cg(&ASMr(st, q + r * 16, acol), hg + (size_t)(q + r * 16) * HID + kk + acol);
                    cp16_ca(&BSMr(st, q + r * 16, acol), Wg + boff[r] + kk);
                }
                CP_COMMIT();
                CP_WAIT(1);
            } else {
                CP_WAIT(0);
            }
            __syncthreads();
            const int st = ch & 1;
            #pragma unroll
            for (int ks = 0; ks < 8; ks++) {
                const int k = ks * 16;
                unsigned a[2][4];
                #pragma unroll
                for (int mi = 0; mi < 2; mi++) {
                    const int r0 = wm * 32 + mi * 16 + g;
                    a[mi][0] = *(const unsigned*)&ASMr(st, r0, k + 2 * t);
                    a[mi][1] = *(const unsigned*)&ASMr(st, r0 + 8, k + 2 * t);
                    a[mi][2] = *(const unsigned*)&ASMr(st, r0, k + 8 + 2 * t);
                    a[mi][3] = *(const unsigned*)&ASMr(st, r0 + 8, k + 8 + 2 * t);
                }
                #pragma unroll
                for (int ni = 0; ni < 2; ni++) {
                    const int n = wn * 16 + ni * 8 + g;
                    unsigned b[2];
                    b[0] = *(const unsigned*)&BSMr(st, n, k + 2 * t);
                    b[1] = *(const unsigned*)&BSMr(st, n, k + 8 + 2 * t);
                    mma_16816(acc[0][ni], a[0], b);
                    mma_16816(acc[1][ni], a[1], b);
                }
            }
            __syncthreads();
        }

        // gates -> gsm
        #pragma unroll
        for (int mi = 0; mi < 2; mi++) {
            const int r0 = wm * 32 + mi * 16 + g;
            #pragma unroll
            for (int ni = 0; ni < 2; ni++) {
                const int col = wn * 16 + ni * 8 + 2 * t;
                GSMr(r0, col)         = acc[mi][ni][0];
                GSMr(r0, col + 1)     = acc[mi][ni][1];
                GSMr(r0 + 8, col)     = acc[mi][ni][2];
                GSMr(r0 + 8, col + 1) = acc[mi][ni][3];
            }
        }
        __syncthreads();

        // LSTM cell: 1024 (b, ul) pairs
        #pragma unroll
        for (int it = tid; it < 1024; it += 256) {
            const int b = it >> 4, ul = it & 15;
            const float gi = GSMr(b, ul)      + __half2float(PSMr(b, ul));
            const float gf = GSMr(b, 16 + ul) + __half2float(PSMr(b, 16 + ul));
            const float gg = GSMr(b, 32 + ul) + __half2float(PSMr(b, 32 + ul));
            const float go = GSMr(b, 48 + ul) + __half2float(PSMr(b, 48 + ul));
            const float si = fsig(gi);
            const float sf = fsig(gf);
            const float so = fsig(go);
            const float c = sf * csm[it] + si * ftanh(gg);
            csm[it] = c;
            g_h[(s + 1) & 1][b * HID + u0 + ul] = __float2half_rn(so * ftanh(c));
        }

        __threadfence();
        __syncthreads();
        if (tid == 0) {
            atomicAdd(&g_bar, 1u);
            const unsigned target = (unsigned)(s + 1) * RBLK;
            while ((int)(*((volatile unsigned*)&g_bar) - target) < 0) { __nanosleep(32); }
        }
        __syncthreads();
    }
#undef ASMr
#undef BSMr
#undef PSMr
#undef GSMr
}

// ---------------- phase C: MLP head ----------------
__global__ __launch_bounds__(256) void k_head(const float* __restrict__ W1,
                                              const float* __restrict__ p2a,
                                              const float* __restrict__ p2b,
                                              const float* __restrict__ b2,
                                              float* __restrict__ out) {
    __shared__ float hsh[HID];
    __shared__ float red[256];
    const int b = blockIdx.x, tid = threadIdx.x;
    const __half* hh = g_h[S_LEN & 1] + b * HID;   // final parity 0
    for (int i = tid; i < HID; i += 256) hsh[i] = __half2float(hh[i]);
    __syncthreads();

    const float* b1p = g_sel256 ? p2a : p2b;
    const float* W2p = g_sel256 ? p2b : p2a;

    float acc = b1p[tid];
    const float4* w = (const float4*)(W1 + (size_t)tid * HID);
    #pragma unroll 4
    for (int k = 0; k < HID / 4; k++) {
        float4 v = w[k];
        acc += v.x * hsh[k * 4] + v.y * hsh[k * 4 + 1] + v.z * hsh[k * 4 + 2] + v.w * hsh[k * 4 + 3];
    }
    red[tid] = fmaxf(acc, 0.f) * W2p[tid];
    __syncthreads();
    for (int srd = 128; srd > 0; srd >>= 1) {
        if (tid < srd) red[tid] += red[tid + srd];
        __syncthreads();
    }
    if (tid == 0) out[b] = 1.f / (1.f + expf(-(red[0] + b2[0])));
}

// ---------------- launch: bind pointers by element count ----------------
extern "C" void kernel_launch(void* const* d_in, const int* in_sizes, int n_in,
                              void* d_out, int out_size) {
    (void)out_size;
    const int *tokens = 0, *tags = 0;
    const float *emb = 0, *Wih = 0, *Whh = 0, *bih = 0, *bhh = 0, *W1 = 0;
    const float *p2a = 0, *p2b = 0, *b2 = 0;

    for (int i = 0; i < n_in; i++) {
        const long n = in_sizes[i];
        const void* p = d_in[i];
        if (n == 32768)          tokens = (const int*)p;
        else if (n == 512 && !tags) tags = (const int*)p;
        else if (n == 25600000)  emb    = (const float*)p;
        else if (n == 27262976)  Wih    = (const float*)p;
        else if (n == 54525952)  Whh    = (const float*)p;
        else if (n == 53248)     { if (!bih) bih = (const float*)p; else bhh = (const float*)p; }
        else if (n == 262144)    W1     = (const float*)p;
        else if (n == 256)       { if (!p2a) p2a = (const float*)p; else p2b = (const float*)p; }
        else if (n == 1)         b2     = (const float*)p;
    }
    if (!tokens) tokens = (const int*)d_in[0];
    if (!tags)   tags   = (const int*)d_in[1];
    if (!emb)    emb    = (const float*)d_in[2];
    if (!Wih)    Wih    = (const float*)d_in[3];
    if (!Whh)    Whh    = (const float*)d_in[4];
    if (!bih)    bih    = (const float*)d_in[5];
    if (!bhh)    bhh    = (const float*)d_in[6];
    if (!W1)     W1     = (const float*)d_in[7];
    if (!p2a)    p2a    = (const float*)d_in[8];
    if (!p2b)    p2b    = (const float*)d_in[9];
    if (!b2)     b2     = (const float*)d_in[10];
    float* out = (float*)d_out;

    cudaFuncSetAttribute(k_recurrent, cudaFuncAttributeMaxDynamicSharedMemorySize, RSM_BYTES);

    k_prep1<<<2048, 256>>>(Wih, bih, bhh);
    k_prep2<<<4096, 256>>>(Whh, tokens, emb, tags, p2a, p2b);
    k_input_pair<<<dim3(32, 256), 256>>>(tags);
    k_recurrent<<<RBLK, 256, RSM_BYTES>>>(tags);
    k_head<<<BATCH, 256>>>(W1, p2a, p2b, b2, out);
}

// round 15
// speedup vs baseline: 1.1902x; 1.1902x over previous
#include <cuda_runtime.h>
#include <cuda_fp16.h>
#include <cstdint>
#include <cstddef>

#define S_LEN 512
#define BATCH 64
#define EMB   512
#define HID   1024
#define G4    4096
#define NTAG  13
#define RBLK  128

// ---------------- scratch (device globals: no allocs allowed) ----------------
__device__ __half g_Wih16[(size_t)NTAG * G4 * EMB];
__device__ __half g_Whh16[(size_t)NTAG * G4 * HID];
__device__ float  g_bias[NTAG * G4];
__device__ __half g_x16[(size_t)S_LEN * BATCH * EMB];
__device__ __half g_pre16[(size_t)S_LEN * BATCH * G4];
__device__ __half g_h[2][BATCH * HID];
__device__ unsigned int g_bar;
__device__ int g_sel256;

// ---------------- helpers ----------------
__device__ __forceinline__ void cp16_ca(void* dst, const void* src) {
    unsigned d = (unsigned)__cvta_generic_to_shared(dst);
    asm volatile("cp.async.ca.shared.global [%0], [%1], 16;\n" :: "r"(d), "l"(src));
}
__device__ __forceinline__ void cp16_cg(void* dst, const void* src) {
    unsigned d = (unsigned)__cvta_generic_to_shared(dst);
    asm volatile("cp.async.cg.shared.global [%0], [%1], 16;\n" :: "r"(d), "l"(src));
}
#define CP_COMMIT() asm volatile("cp.async.commit_group;\n" ::)
#define CP_WAIT(n)  asm volatile("cp.async.wait_group %0;\n" :: "n"(n))

__device__ __forceinline__ void mma_16816(float d[4], const unsigned a[4], const unsigned b[2]) {
    asm volatile(
        "mma.sync.aligned.m16n8k16.row.col.f32.f16.f16.f32 "
        "{%0,%1,%2,%3}, {%4,%5,%6,%7}, {%8,%9}, {%0,%1,%2,%3};\n"
        : "+f"(d[0]), "+f"(d[1]), "+f"(d[2]), "+f"(d[3])
        : "r"(a[0]), "r"(a[1]), "r"(a[2]), "r"(a[3]), "r"(b[0]), "r"(b[1]));
}

__device__ __forceinline__ float fsig(float x) {
    return __fdividef(1.f, 1.f + __expf(-x));
}
__device__ __forceinline__ float ftanh(float x) {
    return 2.f * __fdividef(1.f, 1.f + __expf(-2.f * x)) - 1.f;
}

// ---------------- prep 1: cast Wih + bias ----------------
__global__ void k_prep1(const float* __restrict__ Wih,
                        const float* __restrict__ bih, const float* __restrict__ bhh) {
    const size_t tid0 = (size_t)blockIdx.x * blockDim.x + threadIdx.x;
    const size_t stride = (size_t)gridDim.x * blockDim.x;
    const size_t n4 = (size_t)NTAG * G4 * EMB / 4;
    for (size_t i = tid0; i < n4; i += stride) {
        float4 a = ((const float4*)Wih)[i];
        __half2* o = (__half2*)(g_Wih16 + i * 4);
        o[0] = __floats2half2_rn(a.x, a.y);
        o[1] = __floats2half2_rn(a.z, a.w);
    }
    for (size_t i = tid0; i < (size_t)NTAG * G4; i += stride)
        g_bias[i] = bih[i] + bhh[i];
}

// ---------------- prep 2: cast Whh + gather x + init + pick ----------------
__global__ void k_prep2(const float* __restrict__ Whh,
                        const int* __restrict__ tokens, const float* __restrict__ emb,
                        const float* __restrict__ p2a, const float* __restrict__ p2b) {
    const size_t tid0 = (size_t)blockIdx.x * blockDim.x + threadIdx.x;
    const size_t stride = (size_t)gridDim.x * blockDim.x;
    const size_t n4 = (size_t)NTAG * G4 * HID / 4;
    for (size_t i = tid0; i < n4; i += stride) {
        float4 a = ((const float4*)Whh)[i];
        __half2* o = (__half2*)(g_Whh16 + i * 4);
        o[0] = __floats2half2_rn(a.x, a.y);
        o[1] = __floats2half2_rn(a.z, a.w);
    }
    const size_t gtot = (size_t)S_LEN * BATCH * (EMB / 4);
    for (size_t idx = tid0; idx < gtot; idx += stride) {
        const int i = (int)(idx & (EMB / 4 - 1));
        const size_t r = idx >> 7;
        const int b = (int)(r & (BATCH - 1));
        const int s = (int)(r >> 6);
        const int tok = tokens[b * S_LEN + s];
        float4 v = ((const float4*)(emb + (size_t)tok * EMB))[i];
        __half2* dst = (__half2*)(g_x16 + ((size_t)s * BATCH + b) * EMB) + i * 2;
        dst[0] = __floats2half2_rn(v.x, v.y);
        dst[1] = __floats2half2_rn(v.z, v.w);
    }
    for (size_t i = tid0; i < BATCH * HID / 2; i += stride)
        ((unsigned*)&g_h[0][0])[i] = 0u;
    if (blockIdx.x == 0 && threadIdx.x == 0) {
        float sa = 0.f, sb = 0.f;
        for (int i = 0; i < 256; i++) { sa += fabsf(p2a[i]); sb += fabsf(p2b[i]); }
        g_sel256 = (sa <= sb) ? 1 : 0;
        g_bar = 0u;
    }
}

// ---------------- phase A: input GEMM (fp16, K=512, 8 chunks of 64) ----------------
__global__ __launch_bounds__(256) void k_input_gemm(const int* __restrict__ tags) {
    __shared__ __half Asm[2][64][72];
    __shared__ __half Bsm[2][128][72];
    __shared__ float  bsm[128];

    const int jt = blockIdx.x;      // 0..31
    const int s  = blockIdx.y;      // 0..511
    const int tid = threadIdx.x;
    const int tag = tags[s];
    const int j0 = jt * 128;

    const __half* Ag = g_x16 + (size_t)s * BATCH * EMB;
    const __half* Bg = g_Wih16 + ((size_t)tag * G4 + (size_t)j0) * EMB;

    if (tid < 128) bsm[tid] = g_bias[tag * G4 + j0 + tid];

    const int arow0 = tid >> 3, acol = (tid & 7) * 8;
    const int brow0 = tid >> 3, bcol = (tid & 7) * 8;

    float acc[2][4][4];
    #pragma unroll
    for (int m = 0; m < 2; m++)
        #pragma unroll
        for (int n = 0; n < 4; n++)
            #pragma unroll
            for (int q = 0; q < 4; q++) acc[m][n][q] = 0.f;

    #pragma unroll
    for (int r = 0; r < 2; r++)
        cp16_ca(&Asm[0][arow0 + r * 32][acol], Ag + (size_t)(arow0 + r * 32) * EMB + acol);
    #pragma unroll
    for (int r = 0; r < 4; r++)
        cp16_ca(&Bsm[0][brow0 + r * 32][bcol], Bg + (size_t)(brow0 + r * 32) * EMB + bcol);
    CP_COMMIT();

    const int wid = tid >> 5, lane = tid & 31;
    const int wm = wid >> 2, wn = wid & 3;
    const int g = lane >> 2, t = lane & 3;

    #pragma unroll 1
    for (int ch = 0; ch < 8; ch++) {
        if (ch < 7) {
            const int kk = (ch + 1) * 64;
            const int st = (ch + 1) & 1;
            #pragma unroll
            for (int r = 0; r < 2; r++)
                cp16_ca(&Asm[st][arow0 + r * 32][acol], Ag + (size_t)(arow0 + r * 32) * EMB + kk + acol);
            #pragma unroll
            for (int r = 0; r < 4; r++)
                cp16_ca(&Bsm[st][brow0 + r * 32][bcol], Bg + (size_t)(brow0 + r * 32) * EMB + kk + bcol);
            CP_COMMIT();
            CP_WAIT(1);
        } else {
            CP_WAIT(0);
        }
        __syncthreads();
        const int st = ch & 1;
        #pragma unroll
        for (int ks = 0; ks < 4; ks++) {
            const int k = ks * 16;
            unsigned a[2][4];
            #pragma unroll
            for (int m = 0; m < 2; m++) {
                const int r0 = wm * 32 + m * 16 + g;
                a[m][0] = *(const unsigned*)&Asm[st][r0][k + 2 * t];
                a[m][1] = *(const unsigned*)&Asm[st][r0 + 8][k + 2 * t];
                a[m][2] = *(const unsigned*)&Asm[st][r0][k + 8 + 2 * t];
                a[m][3] = *(const unsigned*)&Asm[st][r0 + 8][k + 8 + 2 * t];
            }
            #pragma unroll
            for (int nt = 0; nt < 4; nt++) {
                const int n = wn * 32 + nt * 8 + g;
                unsigned b[2];
                b[0] = *(const unsigned*)&Bsm[st][n][k + 2 * t];
                b[1] = *(const unsigned*)&Bsm[st][n][k + 8 + 2 * t];
                mma_16816(acc[0][nt], a[0], b);
                mma_16816(acc[1][nt], a[1], b);
            }
        }
        __syncthreads();
    }

    #pragma unroll
    for (int m = 0; m < 2; m++) {
        const int r0 = wm * 32 + m * 16 + g;
        #pragma unroll
        for (int nt = 0; nt < 4; nt++) {
            const int col = wn * 32 + nt * 8 + 2 * t;
            const float b0v = bsm[col], b1v = bsm[col + 1];
            *(__half2*)&g_pre16[((size_t)s * BATCH + r0) * G4 + j0 + col] =
                __floats2half2_rn(acc[m][nt][0] + b0v, acc[m][nt][1] + b1v);
            *(__half2*)&g_pre16[((size_t)s * BATCH + r0 + 8) * G4 + j0 + col] =
                __floats2half2_rn(acc[m][nt][2] + b0v, acc[m][nt][3] + b1v);
        }
    }
}

// ---------------- phase B: persistent recurrent (128 blocks x 8 units, 4 chunks of 256) ----------------
#define RSM_A   (2 * 64 * 264)                 // halves
#define RSM_B   (2 * 32 * 264)
#define RSM_P   (64 * 32)
#define RSM_G   (64 * 33)                      // floats
#define RSM_BYTES ((RSM_A + RSM_B + RSM_P) * 2 + (RSM_G + 512) * 4 + S_LEN * 4)

__global__ __launch_bounds__(256) void k_recurrent(const int* __restrict__ tags) {
    extern __shared__ __align__(16) unsigned char dsm_raw[];
    __half* Abuf = (__half*)dsm_raw;
    __half* Bbuf = Abuf + RSM_A;
    __half* psm  = Bbuf + RSM_B;
    float*  gsm  = (float*)(psm + RSM_P);
    float*  csm  = gsm + RSM_G;
    int*    tsm  = (int*)(csm + 512);
#define ASMr(st,r,c) Abuf[((st) * 64 + (r)) * 264 + (c)]
#define BSMr(st,r,c) Bbuf[((st) * 32 + (r)) * 264 + (c)]
#define PSMr(r,c)    psm[(r) * 32 + (c)]
#define GSMr(r,c)    gsm[(r) * 33 + (c)]

    const int tid = threadIdx.x;
    const int u0  = blockIdx.x * 8;

    for (int i = tid; i < S_LEN; i += 256) tsm[i] = tags[i];
    for (int i = tid; i < 512; i += 256) csm[i] = 0.f;
    __syncthreads();

    const int wid = tid >> 5, lane = tid & 31;
    const int wm = wid >> 1, wn = wid & 1;     // 4 x 2: M16 x N16 per warp
    const int g = lane >> 2, t = lane & 3;

    // A copy: 64 rows x 256 cols; arow = tid>>2 (0..63), 8 ops: col = (tid&3)*8 + i*32
    const int arow = tid >> 2, ac0 = (tid & 3) * 8;
    // B copy: 32 rows x 256 cols; brow = tid>>3 (0..31), 4 ops: col = (tid&7)*8 + i*64
    const int brow = tid >> 3, bc0 = (tid & 7) * 8;
    const size_t boff = (size_t)((brow >> 3) * 1024 + u0 + (brow & 7)) * HID;
    // pre copy: (batch, gate)
    const int pb = tid >> 2, pg = tid & 3;

    for (int s = 0; s < S_LEN; s++) {
        const int tag = tsm[s];
        const __half* Wg = g_Whh16 + (size_t)tag * G4 * HID;
        const __half* hg = g_h[s & 1];

        float acc[2][4];
        #pragma unroll
        for (int i = 0; i < 2; i++) { acc[i][0] = acc[i][1] = acc[i][2] = acc[i][3] = 0.f; }

        // chunk 0 group: A, B, pre tile
        #pragma unroll
        for (int i = 0; i < 8; i++)
            cp16_cg(&ASMr(0, arow, ac0 + i * 32), hg + (size_t)arow * HID + ac0 + i * 32);
        #pragma unroll
        for (int i = 0; i < 4; i++)
            cp16_ca(&BSMr(0, brow, bc0 + i * 64), Wg + boff + bc0 + i * 64);
        cp16_ca(&PSMr(pb, pg * 8),
                g_pre16 + ((size_t)s * BATCH + pb) * G4 + (size_t)pg * 1024 + u0);
        CP_COMMIT();

        #pragma unroll 1
        for (int ch = 0; ch < 4; ch++) {
            if (ch < 3) {
                const int kk = (ch + 1) * 256;
                const int st = (ch + 1) & 1;
                #pragma unroll
                for (int i = 0; i < 8; i++)
                    cp16_cg(&ASMr(st, arow, ac0 + i * 32), hg + (size_t)arow * HID + kk + ac0 + i * 32);
                #pragma unroll
                for (int i = 0; i < 4; i++)
                    cp16_ca(&BSMr(st, brow, bc0 + i * 64), Wg + boff + kk + bc0 + i * 64);
                CP_COMMIT();
                CP_WAIT(1);
            } else {
                CP_WAIT(0);
            }
            __syncthreads();
            const int st = ch & 1;
            #pragma unroll
            for (int ks = 0; ks < 16; ks++) {
                const int k = ks * 16;
                unsigned a[4];
                const int r0 = wm * 16 + g;
                a[0] = *(const unsigned*)&ASMr(st, r0, k + 2 * t);
                a[1] = *(const unsigned*)&ASMr(st, r0 + 8, k + 2 * t);
                a[2] = *(const unsigned*)&ASMr(st, r0, k + 8 + 2 * t);
                a[3] = *(const unsigned*)&ASMr(st, r0 + 8, k + 8 + 2 * t);
                #pragma unroll
                for (int nt = 0; nt < 2; nt++) {
                    const int n = wn * 16 + nt * 8 + g;
                    unsigned b[2];
                    b[0] = *(const unsigned*)&BSMr(st, n, k + 2 * t);
                    b[1] = *(const unsigned*)&BSMr(st, n, k + 8 + 2 * t);
                    mma_16816(acc[nt], a, b);
                }
            }
            __syncthreads();
        }

        // gates -> gsm
        {
            const int r0 = wm * 16 + g;
            #pragma unroll
            for (int nt = 0; nt < 2; nt++) {
                const int col = wn * 16 + nt * 8 + 2 * t;
                GSMr(r0, col)         = acc[nt][0];
                GSMr(r0, col + 1)     = acc[nt][1];
                GSMr(r0 + 8, col)     = acc[nt][2];
                GSMr(r0 + 8, col + 1) = acc[nt][3];
            }
        }
        __syncthreads();

        // LSTM cell: 512 (b, ul) pairs
        #pragma unroll
        for (int it = tid; it < 512; it += 256) {
            const int b = it >> 3, ul = it & 7;
            const float gi = GSMr(b, ul)      + __half2float(PSMr(b, ul));
            const float gf = GSMr(b, 8 + ul)  + __half2float(PSMr(b, 8 + ul));
            const float gg = GSMr(b, 16 + ul) + __half2float(PSMr(b, 16 + ul));
            const float go = GSMr(b, 24 + ul) + __half2float(PSMr(b, 24 + ul));
            const float si = fsig(gi);
            const float sf = fsig(gf);
            const float so = fsig(go);
            const float c = sf * csm[it] + si * ftanh(gg);
            csm[it] = c;
            g_h[(s + 1) & 1][b * HID + u0 + ul] = __float2half_rn(so * ftanh(c));
        }

        __threadfence();
        __syncthreads();
        if (tid == 0) {
            atomicAdd(&g_bar, 1u);
            const unsigned target = (unsigned)(s + 1) * RBLK;
            while ((int)(*((volatile unsigned*)&g_bar) - target) < 0) { __nanosleep(32); }
        }
        __syncthreads();
    }
#undef ASMr
#undef BSMr
#undef PSMr
#undef GSMr
}

// ---------------- phase C: MLP head ----------------
__global__ __launch_bounds__(256) void k_head(const float* __restrict__ W1,
                                              const float* __restrict__ p2a,
                                              const float* __restrict__ p2b,
                                              const float* __restrict__ b2,
                                              float* __restrict__ out) {
    __shared__ float hsh[HID];
    __shared__ float red[256];
    const int b = blockIdx.x, tid = threadIdx.x;
    const __half* hh = g_h[S_LEN & 1] + b * HID;   // final parity 0
    for (int i = tid; i < HID; i += 256) hsh[i] = __half2float(hh[i]);
    __syncthreads();

    const float* b1p = g_sel256 ? p2a : p2b;
    const float* W2p = g_sel256 ? p2b : p2a;

    float acc = b1p[tid];
    const float4* w = (const float4*)(W1 + (size_t)tid * HID);
    #pragma unroll 4
    for (int k = 0; k < HID / 4; k++) {
        float4 v = w[k];
        acc += v.x * hsh[k * 4] + v.y * hsh[k * 4 + 1] + v.z * hsh[k * 4 + 2] + v.w * hsh[k * 4 + 3];
    }
    red[tid] = fmaxf(acc, 0.f) * W2p[tid];
    __syncthreads();
    for (int srd = 128; srd > 0; srd >>= 1) {
        if (tid < srd) red[tid] += red[tid + srd];
        __syncthreads();
    }
    if (tid == 0) out[b] = 1.f / (1.f + expf(-(red[0] + b2[0])));
}

// ---------------- launch: bind pointers by element count ----------------
extern "C" void kernel_launch(void* const* d_in, const int* in_sizes, int n_in,
                              void* d_out, int out_size) {
    (void)out_size;
    const int *tokens = 0, *tags = 0;
    const float *emb = 0, *Wih = 0, *Whh = 0, *bih = 0, *bhh = 0, *W1 = 0;
    const float *p2a = 0, *p2b = 0, *b2 = 0;

    for (int i = 0; i < n_in; i++) {
        const long n = in_sizes[i];
        const void* p = d_in[i];
        if (n == 32768)          tokens = (const int*)p;
        else if (n == 512 && !tags) tags = (const int*)p;
        else if (n == 25600000)  emb    = (const float*)p;
        else if (n == 27262976)  Wih    = (const float*)p;
        else if (n == 54525952)  Whh    = (const float*)p;
        else if (n == 53248)     { if (!bih) bih = (const float*)p; else bhh = (const float*)p; }
        else if (n == 262144)    W1     = (const float*)p;
        else if (n == 256)       { if (!p2a) p2a = (const float*)p; else p2b = (const float*)p; }
        else if (n == 1)         b2     = (const float*)p;
    }
    if (!tokens) tokens = (const int*)d_in[0];
    if (!tags)   tags   = (const int*)d_in[1];
    if (!emb)    emb    = (const float*)d_in[2];
    if (!Wih)    Wih    = (const float*)d_in[3];
    if (!Whh)    Whh    = (const float*)d_in[4];
    if (!bih)    bih    = (const float*)d_in[5];
    if (!bhh)    bhh    = (const float*)d_in[6];
    if (!W1)     W1     = (const float*)d_in[7];
    if (!p2a)    p2a    = (const float*)d_in[8];
    if (!p2b)    p2b    = (const float*)d_in[9];
    if (!b2)     b2     = (const float*)d_in[10];
    float* out = (float*)d_out;

    cudaFuncSetAttribute(k_recurrent, cudaFuncAttributeMaxDynamicSharedMemorySize, RSM_BYTES);

    k_prep1<<<2048, 256>>>(Wih, bih, bhh);
    k_prep2<<<4096, 256>>>(Whh, tokens, emb, p2a, p2b);
    k_input_gemm<<<dim3(32, S_LEN), 256>>>(tags);
    k_recurrent<<<RBLK, 256, RSM_BYTES>>>(tags);
    k_head<<<BATCH, 256>>>(W1, p2a, p2b, b2, out);
}